// round 2
// baseline (speedup 1.0000x reference)
#include <cuda_runtime.h>

#define T_STEPS 1024
#define N_INP   512
#define N_CELLS 4096
#define NBLK    128
#define NTHR    1024

// ---------------- scratch state (static device globals; no allocation) ----------------
__device__ float    g_Z[(size_t)T_STEPS * N_CELLS];   // precomputed Wz @ x_t, 16 MB
__device__ float    g_y[2][N_CELLS];                  // double-buffered pre-relu state
__device__ float    g_u[2];
__device__ float    g_w[2];
__device__ unsigned g_bar;                            // grid barrier counter

// ---------------- init: reset state every call (determinism across graph replays) ----
__global__ void init_kernel() {
    int i = blockIdx.x * blockDim.x + threadIdx.x;
    if (i < N_CELLS) g_y[0][i] = 0.1f;
    if (i == 0) { g_u[0] = 0.5f; g_w[0] = 1.0f; g_bar = 0u; }
}

// ---------------- Z = X(T,K) @ Wz(N,K)^T : register-tiled fp32 GEMM ------------------
// BM=64 (t), BN=64 (n), BK=16; 16x16 threads, 4x4 micro-tile per thread.
__global__ void zgemm_kernel(const float* __restrict__ X, const float* __restrict__ W) {
    __shared__ float Xs[16][64];
    __shared__ float Ws[16][64];
    const int tx = threadIdx.x;            // -> n
    const int ty = threadIdx.y;            // -> t
    const int tid = ty * 16 + tx;          // 0..255
    const int t0 = blockIdx.y * 64;
    const int n0 = blockIdx.x * 64;
    const int lrow = tid >> 2;             // 0..63
    const int lk   = (tid & 3) * 4;        // 0,4,8,12

    float acc[4][4];
    #pragma unroll
    for (int i = 0; i < 4; ++i)
        #pragma unroll
        for (int j = 0; j < 4; ++j) acc[i][j] = 0.f;

    for (int k0 = 0; k0 < N_INP; k0 += 16) {
        float4 xv = *(const float4*)(X + (size_t)(t0 + lrow) * N_INP + k0 + lk);
        float4 wv = *(const float4*)(W + (size_t)(n0 + lrow) * N_INP + k0 + lk);
        __syncthreads();   // previous tile fully consumed before overwrite
        Xs[lk + 0][lrow] = xv.x; Xs[lk + 1][lrow] = xv.y;
        Xs[lk + 2][lrow] = xv.z; Xs[lk + 3][lrow] = xv.w;
        Ws[lk + 0][lrow] = wv.x; Ws[lk + 1][lrow] = wv.y;
        Ws[lk + 2][lrow] = wv.z; Ws[lk + 3][lrow] = wv.w;
        __syncthreads();
        #pragma unroll
        for (int kk = 0; kk < 16; ++kk) {
            float xm[4], wn[4];
            #pragma unroll
            for (int i = 0; i < 4; ++i) xm[i] = Xs[kk][ty * 4 + i];
            #pragma unroll
            for (int j = 0; j < 4; ++j) wn[j] = Ws[kk][tx * 4 + j];
            #pragma unroll
            for (int i = 0; i < 4; ++i)
                #pragma unroll
                for (int j = 0; j < 4; ++j)
                    acc[i][j] = fmaf(xm[i], wn[j], acc[i][j]);
        }
    }
    #pragma unroll
    for (int i = 0; i < 4; ++i)
        #pragma unroll
        for (int j = 0; j < 4; ++j)
            g_Z[(size_t)(t0 + ty * 4 + i) * N_CELLS + (n0 + tx * 4 + j)] = acc[i][j];
}

// ---------------- persistent recurrence kernel: 1024 steps, 1 barrier/step ----------
__global__ void __launch_bounds__(NTHR, 1) step_kernel(
    const float* __restrict__ Wy, const float* __restrict__ Wx,
    const float* __restrict__ a_shift, const float* __restrict__ b,
    float* __restrict__ out)
{
    __shared__ float yp[N_CELLS];   // relu(y_t), 16 KB
    __shared__ float red[32];

    const int tid  = threadIdx.x;
    const int wid  = tid >> 5;
    const int lane = tid & 31;
    const int row  = blockIdx.x * 32 + wid;          // 0..4095, warp-per-row

    const float4* __restrict__ wy4 = (const float4*)(Wy + (size_t)row * N_CELLS);
    const float4* __restrict__ wx4 = (const float4*)(Wx + (size_t)row * N_CELLS);
    const float4* yp4 = (const float4*)yp;

    float* out_us = out + (size_t)T_STEPS * N_CELLS;
    float* out_ws = out_us + T_STEPS;

    for (int t = 0; t < T_STEPS; ++t) {
        const int cur = t & 1;
        const int nxt = cur ^ 1;

        // stage y_plus in SMEM
        const float* yc = g_y[cur];
        #pragma unroll
        for (int i = tid; i < N_CELLS; i += NTHR) yp[i] = fmaxf(yc[i], 0.0f);
        __syncthreads();

        // block 0: normalization-pool scalar dynamics (needs sum(y_plus^2))
        if (blockIdx.x == 0) {
            float s = 0.f;
            #pragma unroll
            for (int i = tid; i < N_CELLS; i += NTHR) { float v = yp[i]; s = fmaf(v, v, s); }
            #pragma unroll
            for (int o = 16; o > 0; o >>= 1) s += __shfl_xor_sync(0xffffffffu, s, o);
            if (lane == 0) red[wid] = s;
            __syncthreads();
            if (wid == 0) {
                float v = red[lane];
                #pragma unroll
                for (int o = 16; o > 0; o >>= 1) v += __shfl_xor_sync(0xffffffffu, v, o);
                if (lane == 0) {
                    const float S  = v;
                    const float u  = g_u[cur];
                    const float w  = g_w[cur];
                    const float bp = fmaxf(b[t], 0.f);
                    const float up = fminf(u, 1.f);
                    const float wp = fmaxf(w, 0.f);
                    const float r  = bp * 0.1f / (bp + up);          // b+ * sigma / (b+ + u+)
                    const float du = 0.1f * (-u + u * (S + r * r));  // dt/tau_u = 0.1
                    const float u_new   = u + du;
                    const float du_plus = fmaxf(u_new, 0.f) - up;
                    const float w_new   = w + 0.5f * (-w + wp * up + 1.f + du_plus); // dt/tau_w=0.5, alpha=1
                    g_u[nxt] = u_new;  g_w[nxt] = w_new;
                    out_us[t] = u_new; out_ws[t] = w_new;
                }
            }
        }

        // warp-per-row dual dot product: yy = Wy[row,:]·y+ , xy = Wx[row,:]·y+
        float accY = 0.f, accX = 0.f;
        #pragma unroll 4
        for (int j = lane; j < N_CELLS / 4; j += 32) {
            const float4 a4 = wy4[j];
            const float4 c4 = wx4[j];
            const float4 y4 = yp4[j];
            accY = fmaf(a4.x, y4.x, accY); accY = fmaf(a4.y, y4.y, accY);
            accY = fmaf(a4.z, y4.z, accY); accY = fmaf(a4.w, y4.w, accY);
            accX = fmaf(c4.x, y4.x, accX); accX = fmaf(c4.y, y4.y, accX);
            accX = fmaf(c4.z, y4.z, accX); accX = fmaf(c4.w, y4.w, accX);
        }
        #pragma unroll
        for (int o = 16; o > 0; o >>= 1) {
            accY += __shfl_xor_sync(0xffffffffu, accY, o);
            accX += __shfl_xor_sync(0xffffffffu, accX, o);
        }

        if (lane == 0) {
            const float y_old = g_y[cur][row];
            const float z     = g_Z[(size_t)t * N_CELLS + row];
            const float bp    = fmaxf(b[t], 0.f);
            const float at    = a_shift[t];
            const float wp    = fmaxf(g_w[cur], 0.f);
            const float inv1b = 1.0f / (1.0f + bp);
            // dt/tau_y = 0.5, rec_scale = 1
            const float dy    = 0.5f * (-y_old + bp * inv1b * z + (inv1b / wp) * accY) + at * accX;
            const float y_new = y_old + dy;
            g_y[nxt][row] = y_new;
            out[(size_t)t * N_CELLS + row] = fmaxf(y_new, 0.f);
        }

        // ---- grid barrier (monotone counter; reset by init_kernel each call) ----
        __syncthreads();
        if (tid == 0) {
            __threadfence();
            atomicAdd(&g_bar, 1u);
            const unsigned target = (unsigned)(t + 1) * NBLK;
            while (*(volatile unsigned*)&g_bar < target) { }
            __threadfence();
        }
        __syncthreads();
    }
}

// ---------------- launch ------------------------------------------------------------
extern "C" void kernel_launch(void* const* d_in, const int* in_sizes, int n_in,
                              void* d_out, int out_size)
{
    const float* dir_input = (const float*)d_in[0];   // [T, N_IN]
    const float* a_shift   = (const float*)d_in[1];   // [T]
    const float* b         = (const float*)d_in[2];   // [T]
    const float* Wz        = (const float*)d_in[3];   // [N_CELLS, N_IN]
    const float* Wy        = (const float*)d_in[4];   // [N_CELLS, N_CELLS]
    const float* Wx        = (const float*)d_in[5];   // [N_CELLS, N_CELLS]
    float* out = (float*)d_out;                       // [T*N_CELLS] ys | [T] us | [T] ws

    (void)in_sizes; (void)n_in; (void)out_size;

    init_kernel<<<4, 1024>>>();

    dim3 gz(N_CELLS / 64, T_STEPS / 64);
    dim3 bz(16, 16);
    zgemm_kernel<<<gz, bz>>>(dir_input, Wz);

    step_kernel<<<NBLK, NTHR>>>(Wy, Wx, a_shift, b, out);
}

// round 3
// speedup vs baseline: 2.3651x; 2.3651x over previous
#include <cuda_runtime.h>
#include <cuda_fp16.h>

#define T_STEPS 1024
#define N_INP   512
#define N_CELLS 4096
#define NBLK    128
#define NTHR    1024

// ---------------- scratch state (static device globals; no allocation) ----------------
__device__ float    g_Z[(size_t)T_STEPS * N_CELLS];            // precomputed Wz @ x_t, 16 MB
__device__ __half   g_Wy16[(size_t)N_CELLS * N_CELLS];         // 33.5 MB
__device__ __half   g_Wx16[(size_t)N_CELLS * N_CELLS];         // 33.5 MB
__device__ float    g_y[2][N_CELLS];                           // double-buffered pre-relu state
__device__ float    g_u[2];
__device__ float    g_w[2];
__device__ unsigned g_bar;                                     // grid barrier counter

// ---------------- init: reset state every call (determinism across graph replays) ----
__global__ void init_kernel() {
    int i = blockIdx.x * blockDim.x + threadIdx.x;
    if (i < N_CELLS) g_y[0][i] = 0.1f;
    if (i == 0) { g_u[0] = 0.5f; g_w[0] = 1.0f; g_bar = 0u; }
}

// ---------------- fp32 -> fp16 weight conversion (once per call) ---------------------
__global__ void convert_kernel(const float* __restrict__ Wy, const float* __restrict__ Wx) {
    const size_t n4 = (size_t)N_CELLS * N_CELLS / 4;
    size_t stride = (size_t)gridDim.x * blockDim.x;
    for (size_t i = (size_t)blockIdx.x * blockDim.x + threadIdx.x; i < n4; i += stride) {
        float4 a = ((const float4*)Wy)[i];
        float4 c = ((const float4*)Wx)[i];
        __half2 a0 = __floats2half2_rn(a.x, a.y);
        __half2 a1 = __floats2half2_rn(a.z, a.w);
        __half2 c0 = __floats2half2_rn(c.x, c.y);
        __half2 c1 = __floats2half2_rn(c.z, c.w);
        ((uint2*)g_Wy16)[i] = make_uint2(*(unsigned*)&a0, *(unsigned*)&a1);
        ((uint2*)g_Wx16)[i] = make_uint2(*(unsigned*)&c0, *(unsigned*)&c1);
    }
}

// ---------------- Z = X(T,K) @ Wz(N,K)^T : register-tiled fp32 GEMM ------------------
__global__ void zgemm_kernel(const float* __restrict__ X, const float* __restrict__ W) {
    __shared__ float Xs[16][64];
    __shared__ float Ws[16][64];
    const int tx = threadIdx.x;            // -> n
    const int ty = threadIdx.y;            // -> t
    const int tid = ty * 16 + tx;          // 0..255
    const int t0 = blockIdx.y * 64;
    const int n0 = blockIdx.x * 64;
    const int lrow = tid >> 2;             // 0..63
    const int lk   = (tid & 3) * 4;        // 0,4,8,12

    float acc[4][4];
    #pragma unroll
    for (int i = 0; i < 4; ++i)
        #pragma unroll
        for (int j = 0; j < 4; ++j) acc[i][j] = 0.f;

    for (int k0 = 0; k0 < N_INP; k0 += 16) {
        float4 xv = *(const float4*)(X + (size_t)(t0 + lrow) * N_INP + k0 + lk);
        float4 wv = *(const float4*)(W + (size_t)(n0 + lrow) * N_INP + k0 + lk);
        __syncthreads();
        Xs[lk + 0][lrow] = xv.x; Xs[lk + 1][lrow] = xv.y;
        Xs[lk + 2][lrow] = xv.z; Xs[lk + 3][lrow] = xv.w;
        Ws[lk + 0][lrow] = wv.x; Ws[lk + 1][lrow] = wv.y;
        Ws[lk + 2][lrow] = wv.z; Ws[lk + 3][lrow] = wv.w;
        __syncthreads();
        #pragma unroll
        for (int kk = 0; kk < 16; ++kk) {
            float xm[4], wn[4];
            #pragma unroll
            for (int i = 0; i < 4; ++i) xm[i] = Xs[kk][ty * 4 + i];
            #pragma unroll
            for (int j = 0; j < 4; ++j) wn[j] = Ws[kk][tx * 4 + j];
            #pragma unroll
            for (int i = 0; i < 4; ++i)
                #pragma unroll
                for (int j = 0; j < 4; ++j)
                    acc[i][j] = fmaf(xm[i], wn[j], acc[i][j]);
        }
    }
    #pragma unroll
    for (int i = 0; i < 4; ++i)
        #pragma unroll
        for (int j = 0; j < 4; ++j)
            g_Z[(size_t)(t0 + ty * 4 + i) * N_CELLS + (n0 + tx * 4 + j)] = acc[i][j];
}

// ---------------- persistent recurrence kernel: 1024 steps, 1 barrier/step ----------
__global__ void __launch_bounds__(NTHR, 1) step_kernel(
    const float* __restrict__ a_shift, const float* __restrict__ b,
    float* __restrict__ out)
{
    __shared__ float yp[N_CELLS];   // relu(y_t), 16 KB
    __shared__ float red[32];

    const int tid  = threadIdx.x;
    const int wid  = tid >> 5;
    const int lane = tid & 31;
    const int row  = blockIdx.x * 32 + wid;          // 0..4095, warp-per-row

    const uint4* __restrict__ wy4 = (const uint4*)(g_Wy16 + (size_t)row * N_CELLS);
    const uint4* __restrict__ wx4 = (const uint4*)(g_Wx16 + (size_t)row * N_CELLS);
    const float4* yp4 = (const float4*)yp;

    float* out_us = out + (size_t)T_STEPS * N_CELLS;
    float* out_ws = out_us + T_STEPS;

    for (int t = 0; t < T_STEPS; ++t) {
        const int cur = t & 1;
        const int nxt = cur ^ 1;

        // stage y_plus in SMEM (L2-coherent loads: state is cross-SM)
        const float* yc = g_y[cur];
        #pragma unroll
        for (int i = tid; i < N_CELLS; i += NTHR) yp[i] = fmaxf(__ldcg(yc + i), 0.0f);
        __syncthreads();

        // block 0: normalization-pool scalar dynamics (needs sum(y_plus^2))
        if (blockIdx.x == 0) {
            float s = 0.f;
            #pragma unroll
            for (int i = tid; i < N_CELLS; i += NTHR) { float v = yp[i]; s = fmaf(v, v, s); }
            #pragma unroll
            for (int o = 16; o > 0; o >>= 1) s += __shfl_xor_sync(0xffffffffu, s, o);
            if (lane == 0) red[wid] = s;
            __syncthreads();
            if (wid == 0) {
                float v = red[lane];
                #pragma unroll
                for (int o = 16; o > 0; o >>= 1) v += __shfl_xor_sync(0xffffffffu, v, o);
                if (lane == 0) {
                    const float S  = v;
                    const float u  = __ldcg(&g_u[cur]);
                    const float w  = __ldcg(&g_w[cur]);
                    const float bp = fmaxf(b[t], 0.f);
                    const float up = fminf(u, 1.f);
                    const float wp = fmaxf(w, 0.f);
                    const float r  = bp * 0.1f / (bp + up);          // b+ * sigma / (b+ + u+)
                    const float du = 0.1f * (-u + u * (S + r * r));  // dt/tau_u = 0.1
                    const float u_new   = u + du;
                    const float du_plus = fmaxf(u_new, 0.f) - up;
                    const float w_new   = w + 0.5f * (-w + wp * up + 1.f + du_plus); // dt/tau_w=0.5, alpha=1
                    __stcg(&g_u[nxt], u_new);
                    __stcg(&g_w[nxt], w_new);
                    out_us[t] = u_new; out_ws[t] = w_new;
                }
            }
        }

        // warp-per-row dual dot: yy = Wy[row,:]·y+ , xy = Wx[row,:]·y+  (fp16 weights, fp32 accum)
        float accY = 0.f, accX = 0.f;
        #pragma unroll 4
        for (int j = lane; j < N_CELLS / 8; j += 32) {
            const uint4 wy = wy4[j];
            const uint4 wx = wx4[j];
            const float4 ya = yp4[2 * j];
            const float4 yb = yp4[2 * j + 1];
            float2 a0 = __half22float2(*(const __half2*)&wy.x);
            float2 a1 = __half22float2(*(const __half2*)&wy.y);
            float2 a2 = __half22float2(*(const __half2*)&wy.z);
            float2 a3 = __half22float2(*(const __half2*)&wy.w);
            float2 c0 = __half22float2(*(const __half2*)&wx.x);
            float2 c1 = __half22float2(*(const __half2*)&wx.y);
            float2 c2 = __half22float2(*(const __half2*)&wx.z);
            float2 c3 = __half22float2(*(const __half2*)&wx.w);
            accY = fmaf(a0.x, ya.x, accY); accY = fmaf(a0.y, ya.y, accY);
            accY = fmaf(a1.x, ya.z, accY); accY = fmaf(a1.y, ya.w, accY);
            accY = fmaf(a2.x, yb.x, accY); accY = fmaf(a2.y, yb.y, accY);
            accY = fmaf(a3.x, yb.z, accY); accY = fmaf(a3.y, yb.w, accY);
            accX = fmaf(c0.x, ya.x, accX); accX = fmaf(c0.y, ya.y, accX);
            accX = fmaf(c1.x, ya.z, accX); accX = fmaf(c1.y, ya.w, accX);
            accX = fmaf(c2.x, yb.x, accX); accX = fmaf(c2.y, yb.y, accX);
            accX = fmaf(c3.x, yb.z, accX); accX = fmaf(c3.y, yb.w, accX);
        }
        #pragma unroll
        for (int o = 16; o > 0; o >>= 1) {
            accY += __shfl_xor_sync(0xffffffffu, accY, o);
            accX += __shfl_xor_sync(0xffffffffu, accX, o);
        }

        if (lane == 0) {
            const float y_old = __ldcg(&g_y[cur][row]);
            const float z     = g_Z[(size_t)t * N_CELLS + row];
            const float bp    = fmaxf(b[t], 0.f);
            const float at    = a_shift[t];
            const float wp    = fmaxf(__ldcg(&g_w[cur]), 0.f);
            const float inv1b = 1.0f / (1.0f + bp);
            // dt/tau_y = 0.5, rec_scale = 1
            const float dy    = 0.5f * (-y_old + bp * inv1b * z + (inv1b / wp) * accY) + at * accX;
            const float y_new = y_old + dy;
            __stcg(&g_y[nxt][row], y_new);
            out[(size_t)t * N_CELLS + row] = fmaxf(y_new, 0.f);
        }

        // ---- grid barrier (monotone counter; reset by init_kernel each call) ----
        __syncthreads();
        if (tid == 0) {
            __threadfence();
            atomicAdd(&g_bar, 1u);
            const unsigned target = (unsigned)(t + 1) * NBLK;
            while (*(volatile unsigned*)&g_bar < target) { }
            __threadfence();
        }
        __syncthreads();
    }
}

// ---------------- launch ------------------------------------------------------------
extern "C" void kernel_launch(void* const* d_in, const int* in_sizes, int n_in,
                              void* d_out, int out_size)
{
    const float* dir_input = (const float*)d_in[0];   // [T, N_IN]
    const float* a_shift   = (const float*)d_in[1];   // [T]
    const float* b         = (const float*)d_in[2];   // [T]
    const float* Wz        = (const float*)d_in[3];   // [N_CELLS, N_IN]
    const float* Wy        = (const float*)d_in[4];   // [N_CELLS, N_CELLS]
    const float* Wx        = (const float*)d_in[5];   // [N_CELLS, N_CELLS]
    float* out = (float*)d_out;                       // [T*N_CELLS] ys | [T] us | [T] ws

    (void)in_sizes; (void)n_in; (void)out_size;

    init_kernel<<<4, 1024>>>();
    convert_kernel<<<1024, 256>>>(Wy, Wx);

    dim3 gz(N_CELLS / 64, T_STEPS / 64);
    dim3 bz(16, 16);
    zgemm_kernel<<<gz, bz>>>(dir_input, Wz);

    step_kernel<<<NBLK, NTHR>>>(a_shift, b, out);
}

// round 4
// speedup vs baseline: 2.6708x; 1.1292x over previous
#include <cuda_runtime.h>
#include <cuda_fp16.h>

#define T_STEPS 1024
#define N_INP   512
#define N_CELLS 4096
#define NBLK    128
#define NTHR    512            // 16 warps/block, 2 rows/warp -> 4096 rows
#define NWARP   16

// ---------------- scratch state (static device globals; no allocation) ----------------
__device__ float    g_Z[(size_t)T_STEPS * N_CELLS];            // precomputed Wz @ x_t, 16 MB
__device__ __half   g_Wy16[(size_t)N_CELLS * N_CELLS];         // 33.5 MB
__device__ __half   g_Wx16[(size_t)N_CELLS * N_CELLS];         // 33.5 MB
__device__ float    g_y[2][N_CELLS];                           // double-buffered pre-relu state
__device__ float    g_S[T_STEPS + 1];                          // sum(relu(y_t)^2) per step
__device__ float    g_u[2];
__device__ float    g_w[2];
__device__ unsigned g_bar;                                     // grid barrier counter

// ---------------- init: reset state every call (determinism across graph replays) ----
__global__ void init_kernel() {
    int i = blockIdx.x * blockDim.x + threadIdx.x;
    if (i < N_CELLS) g_y[0][i] = 0.1f;
    if (i <= T_STEPS) g_S[i] = (i == 0) ? 4096.0f * 0.01f : 0.0f;
    if (i == 0) { g_u[0] = 0.5f; g_w[0] = 1.0f; g_bar = 0u; }
}

// ---------------- fp32 -> fp16 weight conversion (once per call) ---------------------
__global__ void convert_kernel(const float* __restrict__ Wy, const float* __restrict__ Wx) {
    const size_t n4 = (size_t)N_CELLS * N_CELLS / 4;
    size_t stride = (size_t)gridDim.x * blockDim.x;
    for (size_t i = (size_t)blockIdx.x * blockDim.x + threadIdx.x; i < n4; i += stride) {
        float4 a = ((const float4*)Wy)[i];
        float4 c = ((const float4*)Wx)[i];
        __half2 a0 = __floats2half2_rn(a.x, a.y);
        __half2 a1 = __floats2half2_rn(a.z, a.w);
        __half2 c0 = __floats2half2_rn(c.x, c.y);
        __half2 c1 = __floats2half2_rn(c.z, c.w);
        ((uint2*)g_Wy16)[i] = make_uint2(*(unsigned*)&a0, *(unsigned*)&a1);
        ((uint2*)g_Wx16)[i] = make_uint2(*(unsigned*)&c0, *(unsigned*)&c1);
    }
}

// ---------------- Z = X(T,K) @ Wz(N,K)^T : register-tiled fp32 GEMM ------------------
__global__ void zgemm_kernel(const float* __restrict__ X, const float* __restrict__ W) {
    __shared__ float Xs[16][64];
    __shared__ float Ws[16][64];
    const int tx = threadIdx.x;
    const int ty = threadIdx.y;
    const int tid = ty * 16 + tx;
    const int t0 = blockIdx.y * 64;
    const int n0 = blockIdx.x * 64;
    const int lrow = tid >> 2;
    const int lk   = (tid & 3) * 4;

    float acc[4][4];
    #pragma unroll
    for (int i = 0; i < 4; ++i)
        #pragma unroll
        for (int j = 0; j < 4; ++j) acc[i][j] = 0.f;

    for (int k0 = 0; k0 < N_INP; k0 += 16) {
        float4 xv = *(const float4*)(X + (size_t)(t0 + lrow) * N_INP + k0 + lk);
        float4 wv = *(const float4*)(W + (size_t)(n0 + lrow) * N_INP + k0 + lk);
        __syncthreads();
        Xs[lk + 0][lrow] = xv.x; Xs[lk + 1][lrow] = xv.y;
        Xs[lk + 2][lrow] = xv.z; Xs[lk + 3][lrow] = xv.w;
        Ws[lk + 0][lrow] = wv.x; Ws[lk + 1][lrow] = wv.y;
        Ws[lk + 2][lrow] = wv.z; Ws[lk + 3][lrow] = wv.w;
        __syncthreads();
        #pragma unroll
        for (int kk = 0; kk < 16; ++kk) {
            float xm[4], wn[4];
            #pragma unroll
            for (int i = 0; i < 4; ++i) xm[i] = Xs[kk][ty * 4 + i];
            #pragma unroll
            for (int j = 0; j < 4; ++j) wn[j] = Ws[kk][tx * 4 + j];
            #pragma unroll
            for (int i = 0; i < 4; ++i)
                #pragma unroll
                for (int j = 0; j < 4; ++j)
                    acc[i][j] = fmaf(xm[i], wn[j], acc[i][j]);
        }
    }
    #pragma unroll
    for (int i = 0; i < 4; ++i)
        #pragma unroll
        for (int j = 0; j < 4; ++j)
            g_Z[(size_t)(t0 + ty * 4 + i) * N_CELLS + (n0 + tx * 4 + j)] = acc[i][j];
}

// ---------------- persistent recurrence kernel: 1024 steps, 1 barrier/step ----------
// 16 warps/block, 2 adjacent rows per warp. y staged once in SMEM serves 4 dots/warp.
__global__ void __launch_bounds__(NTHR) step_kernel(
    const float* __restrict__ a_shift, const float* __restrict__ b,
    float* __restrict__ out)
{
    __shared__ float yp[N_CELLS];      // relu(y_t), 16 KB
    __shared__ float sred[NWARP];      // per-warp sum(y_new+^2) contribution
    __shared__ float sh_scal[4];       // [0]=w+, [1]=b+, [2]=a_t, [3]=1/(1+b+)

    const int tid  = threadIdx.x;
    const int wid  = tid >> 5;
    const int lane = tid & 31;
    const int gwid = blockIdx.x * NWARP + wid;       // 0..2047
    const int row0 = gwid * 2;                        // even row; row1 = row0+1

    const uint4* __restrict__ wy0p = (const uint4*)(g_Wy16 + (size_t)row0 * N_CELLS);
    const uint4* __restrict__ wy1p = (const uint4*)(g_Wy16 + (size_t)(row0 + 1) * N_CELLS);
    const uint4* __restrict__ wx0p = (const uint4*)(g_Wx16 + (size_t)row0 * N_CELLS);
    const uint4* __restrict__ wx1p = (const uint4*)(g_Wx16 + (size_t)(row0 + 1) * N_CELLS);
    const float4* yp4 = (const float4*)yp;

    float* out_us = out + (size_t)T_STEPS * N_CELLS;
    float* out_ws = out_us + T_STEPS;

    for (int t = 0; t < T_STEPS; ++t) {
        const int cur = t & 1;
        const int nxt = cur ^ 1;

        // ---- stage relu(y) into SMEM (float4, L2-coherent) + per-block scalars ----
        {
            const float4* yc4 = (const float4*)g_y[cur];
            #pragma unroll
            for (int i = tid; i < N_CELLS / 4; i += NTHR) {
                float4 v;
                v.x = __ldcg(&yc4[i].x); v.y = __ldcg(&yc4[i].y);
                v.z = __ldcg(&yc4[i].z); v.w = __ldcg(&yc4[i].w);
                ((float4*)yp)[i] = make_float4(fmaxf(v.x, 0.f), fmaxf(v.y, 0.f),
                                               fmaxf(v.z, 0.f), fmaxf(v.w, 0.f));
            }
            if (tid == 0) {
                const float wcur = __ldcg(&g_w[cur]);
                const float bp   = fmaxf(b[t], 0.f);
                sh_scal[0] = fmaxf(wcur, 0.f);
                sh_scal[1] = bp;
                sh_scal[2] = a_shift[t];
                sh_scal[3] = 1.0f / (1.0f + bp);
            }
        }
        __syncthreads();

        // ---- block 0 / warp 0 / lane 0: u & w scalar dynamics (S precomputed) ----
        if (blockIdx.x == 0 && tid == 0) {
            const float S  = __ldcg(&g_S[t]);
            const float u  = __ldcg(&g_u[cur]);
            const float w  = __ldcg(&g_w[cur]);
            const float bp = sh_scal[1];
            const float up = fminf(u, 1.f);
            const float wp = fmaxf(w, 0.f);
            const float r  = bp * 0.1f / (bp + up);          // b+ * sigma / (b+ + u+)
            const float du = 0.1f * (-u + u * (S + r * r));  // dt/tau_u = 0.1
            const float u_new   = u + du;
            const float du_plus = fmaxf(u_new, 0.f) - up;
            const float w_new   = w + 0.5f * (-w + wp * up + 1.f + du_plus); // dt/tau_w=0.5
            __stcg(&g_u[nxt], u_new);
            __stcg(&g_w[nxt], w_new);
            out_us[t] = u_new; out_ws[t] = w_new;
        }

        // ---- dual-row dual-matrix dot products (fp16 weights, fp32 accum) ----
        float aY0 = 0.f, aY1 = 0.f, aX0 = 0.f, aX1 = 0.f;
        #pragma unroll 4
        for (int j = lane; j < N_CELLS / 8; j += 32) {
            const uint4 wy0 = wy0p[j];
            const uint4 wy1 = wy1p[j];
            const uint4 wx0 = wx0p[j];
            const uint4 wx1 = wx1p[j];
            const float4 ya = yp4[2 * j];
            const float4 yb = yp4[2 * j + 1];

            float2 h;
            h = __half22float2(*(const __half2*)&wy0.x); aY0 = fmaf(h.x, ya.x, aY0); aY0 = fmaf(h.y, ya.y, aY0);
            h = __half22float2(*(const __half2*)&wy0.y); aY0 = fmaf(h.x, ya.z, aY0); aY0 = fmaf(h.y, ya.w, aY0);
            h = __half22float2(*(const __half2*)&wy0.z); aY0 = fmaf(h.x, yb.x, aY0); aY0 = fmaf(h.y, yb.y, aY0);
            h = __half22float2(*(const __half2*)&wy0.w); aY0 = fmaf(h.x, yb.z, aY0); aY0 = fmaf(h.y, yb.w, aY0);

            h = __half22float2(*(const __half2*)&wy1.x); aY1 = fmaf(h.x, ya.x, aY1); aY1 = fmaf(h.y, ya.y, aY1);
            h = __half22float2(*(const __half2*)&wy1.y); aY1 = fmaf(h.x, ya.z, aY1); aY1 = fmaf(h.y, ya.w, aY1);
            h = __half22float2(*(const __half2*)&wy1.z); aY1 = fmaf(h.x, yb.x, aY1); aY1 = fmaf(h.y, yb.y, aY1);
            h = __half22float2(*(const __half2*)&wy1.w); aY1 = fmaf(h.x, yb.z, aY1); aY1 = fmaf(h.y, yb.w, aY1);

            h = __half22float2(*(const __half2*)&wx0.x); aX0 = fmaf(h.x, ya.x, aX0); aX0 = fmaf(h.y, ya.y, aX0);
            h = __half22float2(*(const __half2*)&wx0.y); aX0 = fmaf(h.x, ya.z, aX0); aX0 = fmaf(h.y, ya.w, aX0);
            h = __half22float2(*(const __half2*)&wx0.z); aX0 = fmaf(h.x, yb.x, aX0); aX0 = fmaf(h.y, yb.y, aX0);
            h = __half22float2(*(const __half2*)&wx0.w); aX0 = fmaf(h.x, yb.z, aX0); aX0 = fmaf(h.y, yb.w, aX0);

            h = __half22float2(*(const __half2*)&wx1.x); aX1 = fmaf(h.x, ya.x, aX1); aX1 = fmaf(h.y, ya.y, aX1);
            h = __half22float2(*(const __half2*)&wx1.y); aX1 = fmaf(h.x, ya.z, aX1); aX1 = fmaf(h.y, ya.w, aX1);
            h = __half22float2(*(const __half2*)&wx1.z); aX1 = fmaf(h.x, yb.x, aX1); aX1 = fmaf(h.y, yb.y, aX1);
            h = __half22float2(*(const __half2*)&wx1.w); aX1 = fmaf(h.x, yb.z, aX1); aX1 = fmaf(h.y, yb.w, aX1);
        }
        #pragma unroll
        for (int o = 16; o > 0; o >>= 1) {
            aY0 += __shfl_xor_sync(0xffffffffu, aY0, o);
            aY1 += __shfl_xor_sync(0xffffffffu, aY1, o);
            aX0 += __shfl_xor_sync(0xffffffffu, aX0, o);
            aX1 += __shfl_xor_sync(0xffffffffu, aX1, o);
        }

        if (lane == 0) {
            const float bp    = sh_scal[1];
            const float at    = sh_scal[2];
            const float inv1b = sh_scal[3];
            const float wp    = sh_scal[0];
            const float zc    = bp * inv1b;
            const float yc    = inv1b / wp;

            const float2 yold = *(const float2*)&g_y[cur][row0];   // written pre-barrier; L2-visible
            const float2 z2   = *(const float2*)&g_Z[(size_t)t * N_CELLS + row0];

            const float yn0 = yold.x + 0.5f * (-yold.x + zc * z2.x + yc * aY0) + at * aX0;
            const float yn1 = yold.y + 0.5f * (-yold.y + zc * z2.y + yc * aY1) + at * aX1;

            float2 st; st.x = yn0; st.y = yn1;
            __stcg((float2*)&g_y[nxt][row0], st);
            const float r0p = fmaxf(yn0, 0.f), r1p = fmaxf(yn1, 0.f);
            *(float2*)&out[(size_t)t * N_CELLS + row0] = make_float2(r0p, r1p);
            sred[wid] = fmaf(r0p, r0p, r1p * r1p);
            __threadfence();   // release y stores before the barrier flag
        }

        // ---- per-block S contribution for step t+1 ----
        __syncthreads();
        if (wid == 0) {
            float v = (lane < NWARP) ? sred[lane] : 0.f;
            #pragma unroll
            for (int o = 8; o > 0; o >>= 1) v += __shfl_xor_sync(0xffffffffu, v, o);
            if (lane == 0) atomicAdd(&g_S[t + 1], v);
        }

        // ---- grid barrier (monotone counter; reset by init_kernel each call) ----
        if (tid == 0) {
            __threadfence();
            atomicAdd(&g_bar, 1u);
            const unsigned target = (unsigned)(t + 1) * NBLK;
            while (*(volatile unsigned*)&g_bar < target) { }
            __threadfence();
        }
        __syncthreads();
    }
}

// ---------------- launch ------------------------------------------------------------
extern "C" void kernel_launch(void* const* d_in, const int* in_sizes, int n_in,
                              void* d_out, int out_size)
{
    const float* dir_input = (const float*)d_in[0];   // [T, N_IN]
    const float* a_shift   = (const float*)d_in[1];   // [T]
    const float* b         = (const float*)d_in[2];   // [T]
    const float* Wz        = (const float*)d_in[3];   // [N_CELLS, N_IN]
    const float* Wy        = (const float*)d_in[4];   // [N_CELLS, N_CELLS]
    const float* Wx        = (const float*)d_in[5];   // [N_CELLS, N_CELLS]
    float* out = (float*)d_out;                       // [T*N_CELLS] ys | [T] us | [T] ws

    (void)in_sizes; (void)n_in; (void)out_size;

    init_kernel<<<6, 1024>>>();
    convert_kernel<<<1024, 256>>>(Wy, Wx);

    dim3 gz(N_CELLS / 64, T_STEPS / 64);
    dim3 bz(16, 16);
    zgemm_kernel<<<gz, bz>>>(dir_input, Wz);

    step_kernel<<<NBLK, NTHR>>>(a_shift, b, out);
}